// round 2
// baseline (speedup 1.0000x reference)
#include <cuda_runtime.h>
#include <math.h>

#define B   32
#define EN  256
#define DX  512
#define DZ  256
#define DM  256
#define H   8
#define HD  32
#define LQ  256   // active queries: l in [256,512), l' = l-256

// scratch (device globals; no allocation allowed)
__device__ __align__(16) float g_Q0[LQ*DM];      // Q0[l'][d] = (Qp[256+l'])@Wq^T + bq
__device__ __align__(16) float g_P0[B*DM];       // P0[b][d]  = pe[b]@Wq^T
__device__ __align__(16) float g_GQT[H*DM*LQ];   // [h][e][l']
__device__ __align__(16) float g_GPb[B*H*DM];    // [b][h][e]
__device__ __align__(16) float g_w[B*LQ];        // attention weight on the state key

// ---------------------------------------------------------------- K1: Q0 (rows l>=256) and P0, pe inline
// 288 rows total: rows 0..255 -> Qp[256+r], rows 256..287 -> pe[r-256]
__global__ void k_q0(const float* __restrict__ Qp, const float* __restrict__ Wq,
                     const float* __restrict__ bq) {
    __shared__ float rowS[32][DM];   // 32KB
    int rt = blockIdx.x;             // 0..8 (tiles of 32 rows)
    int dt = blockIdx.y;             // 0..3 (tiles of 64 output dims)
    int tid = threadIdx.x;

    const float nl = -(logf(10000.0f) / (float)DM);
    #pragma unroll
    for (int k = 0; k < 32; k++) {
        int lin = k * 256 + tid;
        int r = lin >> 8, c = lin & 255;
        int gi = rt * 32 + r;
        float v;
        if (gi < 256) {
            v = Qp[(256 + gi) * DM + c];
        } else {
            int p = gi - 256;                      // pe row (= batch index)
            int i = c >> 1;
            float dv = expf(nl * (float)(2 * i));
            float arg = (float)p * dv;
            v = (c & 1) ? cosf(arg) : sinf(arg);
        }
        rowS[r][c] = v;
    }
    __syncthreads();

    int dl = tid & 63;
    int d = dt * 64 + dl;
    int rbase = (tid >> 6) * 8;
    float bias = (rt < 8) ? bq[d] : 0.0f;          // pe rows get no bias (it cancels via bq on query; P0 excludes bq by construction: bq applied once in Q0)
    float acc[8];
    #pragma unroll
    for (int r = 0; r < 8; r++) acc[r] = bias;

    const float4* Wq4 = (const float4*)(Wq + (size_t)d * DM);
    #pragma unroll 8
    for (int c4 = 0; c4 < 64; c4++) {
        float4 w4 = Wq4[c4];
        #pragma unroll
        for (int r = 0; r < 8; r++) {
            float4 r4 = ((const float4*)&rowS[rbase + r][0])[c4];
            acc[r] += r4.x * w4.x + r4.y * w4.y + r4.z * w4.z + r4.w * w4.w;
        }
    }
    #pragma unroll
    for (int r = 0; r < 8; r++) {
        int gi = rt * 32 + rbase + r;
        if (gi < 256) g_Q0[gi * DM + d] = acc[r];
        else          g_P0[(gi - 256) * DM + d] = acc[r];
    }
}

// ---------------------------------------------------------------- K2: fused GQT + GPb
// blocks 0..127: GQT[h][e][l'] = sum_d Q0[l'][32h+d] * Wk[32h+d][e]
// blocks 128..135: GPb[b][h][e] = sum_d P0[b][32h+d] * Wk[32h+d][e]  (one block per h)
__global__ void k_gkb(const float* __restrict__ Wk) {
    __shared__ float sh[8192 + 1024];   // 36KB, reused per role
    int bx = blockIdx.x;
    int tid = threadIdx.x;

    if (bx < 128) {
        // ---- GQT role ----
        float* wks = sh;                 // [16][32]
        int et = bx & 15;                // e tile (16 e)
        int h  = bx >> 4;
        #pragma unroll
        for (int k = 0; k < 2; k++) {
            int lin = k * 256 + tid;     // 0..511
            int ee = lin >> 5, d = lin & 31;
            wks[ee * 32 + d] = Wk[(h * 32 + d) * DM + et * 16 + ee];
        }
        __syncthreads();

        float4 q4[8];
        const float4* q0p = (const float4*)(g_Q0 + (size_t)tid * DM + h * 32);
        #pragma unroll
        for (int j = 0; j < 8; j++) q4[j] = q0p[j];

        #pragma unroll
        for (int ee = 0; ee < 16; ee++) {
            float acc = 0.0f;
            const float4* wr = (const float4*)&wks[ee * 32];
            #pragma unroll
            for (int j = 0; j < 8; j++) {
                float4 w4 = wr[j];
                acc += q4[j].x * w4.x + q4[j].y * w4.y + q4[j].z * w4.z + q4[j].w * w4.w;
            }
            g_GQT[(h * DM + et * 16 + ee) * LQ + tid] = acc;
        }
    } else {
        // ---- GPb role: one block per h, all 32 batches ----
        float* wk  = sh;                 // [32 d][256 e]
        float* p0s = sh + 8192;          // [32 b][32 d]
        int h = bx - 128;
        #pragma unroll
        for (int d = 0; d < 32; d++)
            wk[d * 256 + tid] = Wk[(h * 32 + d) * DM + tid];
        #pragma unroll
        for (int k = 0; k < 4; k++) {
            int lin = k * 256 + tid;     // 0..1023
            int b = lin >> 5, d = lin & 31;
            p0s[b * 32 + d] = g_P0[b * DM + h * 32 + d];
        }
        __syncthreads();

        #pragma unroll 4
        for (int b = 0; b < 32; b++) {
            float acc = 0.0f;
            #pragma unroll
            for (int d = 0; d < 32; d++)
                acc = fmaf(p0s[b * 32 + d], wk[d * 256 + tid], acc);
            g_GPb[(b * H + h) * DM + tid] = acc;
        }
    }
}

// ---------------------------------------------------------------- K3: delta (+e-sums folded) + newstate for l>=256
// block = (lt 0..7, bg 0..15) handling 2 batches, 32 l' values
__global__ void k_delta(const float* __restrict__ state, const float* __restrict__ obs,
                        float* __restrict__ ns) {
    __shared__ float gps[2 * H * DM];   // 16KB : GPb slices for b0,b1
    __shared__ float red[26 * 256];     // 26KB : phase reduction
    __shared__ float sgp_sh[16];        // sum_e gps per (b,h)
    __shared__ float wsh[64];           // final weights [bsel][lo]
    int lt = blockIdx.x;                // 0..7
    int bg = blockIdx.y;                // 0..15
    int tid = threadIdx.x;
    int b0 = bg * 2;

    #pragma unroll
    for (int k = 0; k < 16; k++)
        gps[k * 256 + tid] = g_GPb[(size_t)b0 * H * DM + k * 256 + tid];
    __syncthreads();

    // sgp_sh[k] = sum_e gps[k*256 + e], k = bsel*8+h  (16 lanes per k, width-16 shuffle)
    {
        int k = tid >> 4, sub = tid & 15;
        float part = 0.0f;
        #pragma unroll
        for (int m = 0; m < 16; m++) part += gps[k * 256 + sub * 16 + m];
        #pragma unroll
        for (int off = 8; off > 0; off >>= 1)
            part += __shfl_down_sync(0xffffffffu, part, off, 16);
        if (sub == 0) sgp_sh[k] = part;
    }

    int lo = tid & 31, p = tid >> 5;
    int lp = lt * 32 + lo;              // l'
    int l = 256 + lp;

    float sdg0[8], sdg1[8], sgq[8];
    #pragma unroll
    for (int h = 0; h < 8; h++) { sdg0[h] = 0.0f; sdg1[h] = 0.0f; sgq[h] = 0.0f; }
    float sd0 = 0.0f, sd1 = 0.0f;

    const float* st0 = state + (size_t)b0 * EN * DX;
    const float* st1 = st0 + (size_t)EN * DX;
    const float* ob0 = obs + (size_t)b0 * EN * DZ;
    const float* ob1 = ob0 + (size_t)EN * DZ;

    #pragma unroll 4
    for (int j = 0; j < 32; j++) {
        int e = p * 32 + j;
        float D0 = st0[(size_t)e * DX + l] - ob0[(size_t)e * DZ + lp];
        float D1 = st1[(size_t)e * DX + l] - ob1[(size_t)e * DZ + lp];
        sd0 += D0; sd1 += D1;
        #pragma unroll
        for (int h = 0; h < 8; h++) {
            float g = g_GQT[(h * DM + e) * LQ + lp];
            sgq[h] += g;
            sdg0[h] = fmaf(D0, g + gps[h * DM + e], sdg0[h]);
            sdg1[h] = fmaf(D1, g + gps[H * DM + h * DM + e], sdg1[h]);
        }
    }

    #pragma unroll
    for (int h = 0; h < 8; h++) {
        red[h * 256 + tid]        = sdg0[h];
        red[(8 + h) * 256 + tid]  = sdg1[h];
        red[(16 + h) * 256 + tid] = sgq[h];
    }
    red[24 * 256 + tid] = sd0;
    red[25 * 256 + tid] = sd1;
    __syncthreads();

    if (tid < 64) {
        int bsel = tid >> 5, lo2 = tid & 31;
        int lp2 = lt * 32 + lo2;
        int b = b0 + bsel;
        float sd = 0.0f;
        #pragma unroll
        for (int q = 0; q < 8; q++) sd += red[(24 + bsel) * 256 + q * 32 + lo2];
        float md = sd * (1.0f / 256.0f);
        float wsum = 0.0f;
        #pragma unroll
        for (int h = 0; h < 8; h++) {
            float sdg = 0.0f, sq = 0.0f;
            #pragma unroll
            for (int q = 0; q < 8; q++) {
                sdg += red[(bsel * 8 + h) * 256 + q * 32 + lo2];
                sq  += red[(16 + h) * 256 + q * 32 + lo2];
            }
            // note: per-thread sgq sums include an extra reduction order but the
            // e-sum of g is b-independent; add the gp part per batch.
            float sg = sq + sgp_sh[bsel * 8 + h];
            // gp part of the D-dot is folded into sdg; the subtraction below removes md * sum(g+gp)
            float delta = (sdg - md * sg) * 0.17677669529663688f;   // 1/sqrt(32)
            wsum += 1.0f / (1.0f + expf(-delta));
        }
        float w = wsum * 0.125f;
        g_w[b * LQ + lp2] = w;
        wsh[bsel * 32 + lo2] = w;
    }
    __syncthreads();

    // ---- fused newstate for l >= 256 (state/obs columns are L1-hot) ----
    if (ns != nullptr) {
        float w0 = wsh[lo];
        float w1 = wsh[32 + lo];
        float* n0 = ns + (size_t)b0 * EN * DX;
        float* n1 = n0 + (size_t)EN * DX;
        #pragma unroll 4
        for (int j = 0; j < 32; j++) {
            int e = p * 32 + j;
            float s0 = st0[(size_t)e * DX + l], o0 = ob0[(size_t)e * DZ + lp];
            float s1 = st1[(size_t)e * DX + l], o1 = ob1[(size_t)e * DZ + lp];
            n0[(size_t)e * DX + l] = o0 + w0 * (s0 - o0);
            n1[(size_t)e * DX + l] = o1 + w1 * (s1 - o1);
        }
    }
}

// ---------------------------------------------------------------- K4: newstate l<256 copy + atten (zero + diag)
__global__ void k_out(const float* __restrict__ state, float* __restrict__ ns,
                      float* __restrict__ att, int cpN) {
    int bx = blockIdx.x;
    if (bx < cpN) {
        // copy l<256 half: new_state[b,e,l] = state[b,e,l]
        int idx = bx * 256 + threadIdx.x;   // 0..524287
        int r = idx >> 6, l4 = idx & 63;    // r = b*EN+e, l4 covers l 0..255 in float4
        ((float4*)ns)[r * 128 + l4] = ((const float4*)state)[r * 128 + l4];
    } else {
        int idx = (bx - cpN) * 256 + threadIdx.x;   // float4 index, 0..3145727
        int s4 = (idx % 192) * 4;
        int bl = idx / 192;
        int l = bl & 511;
        int b = bl >> 9;
        float4 v = make_float4(0.0f, 0.0f, 0.0f, 0.0f);
        int d1 = l - s4;
        if ((unsigned)d1 < 4u) {
            float val = (l < 256) ? 1.0f : g_w[b * LQ + (l - 256)];
            if      (d1 == 0) v.x = val;
            else if (d1 == 1) v.y = val;
            else if (d1 == 2) v.z = val;
            else              v.w = val;
        }
        if (l >= 256) {
            int d2 = (l + 256) - s4;
            if ((unsigned)d2 < 4u) {
                float val = 1.0f - g_w[b * LQ + (l - 256)];
                if      (d2 == 0) v.x = val;
                else if (d2 == 1) v.y = val;
                else if (d2 == 2) v.z = val;
                else              v.w = val;
            }
        }
        ((float4*)att)[idx] = v;
    }
}

// ----------------------------------------------------------------
extern "C" void kernel_launch(void* const* d_in, const int* in_sizes, int n_in,
                              void* d_out, int out_size) {
    const float* state = (const float*)d_in[0];
    const float* obs   = (const float*)d_in[1];
    const float* Qp    = (const float*)d_in[2];
    const float* Wq    = (const float*)d_in[3];
    const float* bq    = (const float*)d_in[4];
    const float* Wk    = (const float*)d_in[5];
    // bk (d_in[6]) provably cancels in the masked softmax — unused.
    float* out = (float*)d_out;

    const int NS = B * EN * DX;        // 4,194,304
    const int AT = B * DX * (DX + DZ); // 12,582,912

    float* ns  = nullptr;
    float* att = nullptr;
    if (out_size >= NS + AT)      { ns = out; att = out + NS; }
    else if (out_size == AT)      { att = out; }
    else                          { ns = out; }

    k_q0   <<<dim3(9, 4),  256>>>(Qp, Wq, bq);
    k_gkb  <<<136,         256>>>(Wk);
    k_delta<<<dim3(8, 16), 256>>>(state, obs, ns);

    int cpN = ns  ? (NS / 2) / 1024 : 0;   // 2048 blocks (8MB of float4 copies)
    int atN = att ? AT / 1024 : 0;         // 12288 blocks
    k_out<<<cpN + atN, 256>>>(state, ns, att, cpN);
}

// round 3
// speedup vs baseline: 1.0871x; 1.0871x over previous
#include <cuda_runtime.h>
#include <math.h>

#define B   32
#define EN  256
#define DX  512
#define DZ  256
#define DM  256
#define H   8
#define LQ  256   // active queries: l in [256,512)
#define NB  128   // persistent blocks (<=148 SMs -> all co-resident, barrier is safe)

// scratch (device globals; no allocation allowed)
__device__ __align__(16) float g_Q0[LQ*DM];      // Q0[l'][d] = Qp[256+l']@Wq^T + bq
__device__ __align__(16) float g_P0[B*DM];       // P0[b][d]  = pe[b]@Wq^T
__device__ __align__(16) float g_GQT[H*DM*LQ];   // [h][e][l']
__device__ __align__(16) float g_GPb[B*H*DM];    // [b][h][e]
__device__ unsigned g_arrive;                    // barrier arrivals (monotonic per launch)
__device__ volatile unsigned g_release;          // barrier release phase
__device__ unsigned g_work;                      // work-steal counter for phase 0

__device__ __forceinline__ void gridbar(unsigned phase) {
    __syncthreads();
    if (threadIdx.x == 0) {
        __threadfence();
        unsigned n = atomicAdd(&g_arrive, 1u) + 1u;
        if (n == phase * NB) {
            __threadfence();
            g_release = phase;
        } else {
            while (g_release < phase) __nanosleep(64);
        }
    }
    __syncthreads();
    __threadfence();
}

__global__ __launch_bounds__(256, 1) void k_fused(
    const float* __restrict__ state, const float* __restrict__ obs,
    const float* __restrict__ Qp, const float* __restrict__ Wq,
    const float* __restrict__ bq, const float* __restrict__ Wk,
    float* __restrict__ ns, float* __restrict__ att)
{
    __shared__ union {
        float rowS[32 * DM];                              // phase 0: 32KB
        float gk[8192 + 1024];                            // phase 1: 36KB
        struct { float gps[2*H*DM]; float red[26*256];
                 float sgp[16]; float wsh[64]; } d;       // phase 2: ~42.3KB
    } sm;
    __shared__ unsigned s_u;

    const int bid = blockIdx.x;
    const int tid = threadIdx.x;

    // ================= Phase 0a: Q0 / P0 projection (blocks 0..35) =================
    if (bid < 36) {
        int rt = bid >> 2, dt = bid & 3;      // rt 0..8, dt 0..3
        const float nl = -(logf(10000.0f) / (float)DM);
        #pragma unroll
        for (int k = 0; k < 32; k++) {
            int lin = k * 256 + tid;
            int r = lin >> 8, c = lin & 255;
            int gi = rt * 32 + r;
            float v;
            if (gi < 256) {
                v = Qp[(256 + gi) * DM + c];
            } else {
                int p = gi - 256;             // pe row (= batch index)
                int i = c >> 1;
                float dv = expf(nl * (float)(2 * i));
                float arg = (float)p * dv;
                v = (c & 1) ? cosf(arg) : sinf(arg);
            }
            sm.rowS[r * DM + c] = v;
        }
        __syncthreads();

        int dl = tid & 63;
        int d = dt * 64 + dl;
        int rbase = (tid >> 6) * 8;
        float bias = (rt < 8) ? bq[d] : 0.0f;   // pe rows (P0) exclude bq
        float acc[8];
        #pragma unroll
        for (int r = 0; r < 8; r++) acc[r] = bias;

        const float4* Wq4 = (const float4*)(Wq + (size_t)d * DM);
        #pragma unroll 8
        for (int c4 = 0; c4 < 64; c4++) {
            float4 w4 = Wq4[c4];
            #pragma unroll
            for (int r = 0; r < 8; r++) {
                float4 r4 = ((const float4*)&sm.rowS[(rbase + r) * DM])[c4];
                acc[r] += r4.x * w4.x + r4.y * w4.y + r4.z * w4.z + r4.w * w4.w;
            }
        }
        #pragma unroll
        for (int r = 0; r < 8; r++) {
            int gi = rt * 32 + rbase + r;
            if (gi < 256) g_Q0[gi * DM + d] = acc[r];
            else          g_P0[(gi - 256) * DM + d] = acc[r];
        }
        __syncthreads();   // done with sm.rowS before streaming loop reuses nothing; keep order clean
    }

    // ================= Phase 0b: work-steal streaming (all blocks) =================
    // att zero-fill (+ diag 1.0 for l<256) and new_state l<256 copy.
    {
        const int Ua = att ? 2048 : 0;    // 2048 units x 8 att rows (row = 192 float4)
        const int Un = ns  ? 256  : 0;    // 256 units x 32 (b,e)-rows x 64 float4
        const int total = Ua + Un;
        for (;;) {
            if (tid == 0) s_u = atomicAdd(&g_work, 1u);
            __syncthreads();
            unsigned u = s_u;
            __syncthreads();
            if (u >= (unsigned)total) break;
            if (u < (unsigned)Ua) {
                int r0 = (int)u * 8;
                if (tid < 192) {
                    #pragma unroll
                    for (int k = 0; k < 8; k++) {
                        int row = r0 + k;               // row = b*512 + l
                        int l = row & 511;
                        float4 v = make_float4(0.f, 0.f, 0.f, 0.f);
                        if (l < 256 && (l >> 2) == tid)
                            ((float*)&v)[l & 3] = 1.0f;
                        ((float4*)att)[(size_t)row * 192 + tid] = v;
                    }
                }
            } else {
                int re0 = ((int)u - Ua) * 32;           // (b*EN+e) row base
                #pragma unroll
                for (int k = 0; k < 8; k++) {
                    int i = k * 256 + tid;
                    int m = i >> 6, c = i & 63;
                    ((float4*)ns)[(size_t)(re0 + m) * 128 + c] =
                        ((const float4*)state)[(size_t)(re0 + m) * 128 + c];
                }
            }
        }
    }
    gridbar(1);

    // ================= Phase 1: GQT (all blocks) + GPb (blocks 0..7) =================
    {
        // GQT tile: et = bid&15, h = bid>>4
        int et = bid & 15, h = bid >> 4;
        float* wks = sm.gk;                 // [16 ee][32 d]
        #pragma unroll
        for (int k = 0; k < 2; k++) {
            int lin = k * 256 + tid;
            int ee = lin >> 5, d = lin & 31;
            wks[ee * 32 + d] = Wk[(h * 32 + d) * DM + et * 16 + ee];
        }
        __syncthreads();

        float4 q4[8];
        const float4* q0p = (const float4*)(g_Q0 + (size_t)tid * DM + h * 32);
        #pragma unroll
        for (int j = 0; j < 8; j++) q4[j] = q0p[j];

        #pragma unroll
        for (int ee = 0; ee < 16; ee++) {
            float acc = 0.0f;
            const float4* wr = (const float4*)&wks[ee * 32];
            #pragma unroll
            for (int j = 0; j < 8; j++) {
                float4 w4 = wr[j];
                acc += q4[j].x * w4.x + q4[j].y * w4.y + q4[j].z * w4.z + q4[j].w * w4.w;
            }
            g_GQT[(h * DM + et * 16 + ee) * LQ + tid] = acc;
        }
        __syncthreads();

        if (bid < 8) {
            // GPb role: h = bid, all 32 batches
            float* wk  = sm.gk;              // [32 d][256 e]
            float* p0s = sm.gk + 8192;       // [32 b][32 d]
            int hh = bid;
            #pragma unroll
            for (int d = 0; d < 32; d++)
                wk[d * 256 + tid] = Wk[(hh * 32 + d) * DM + tid];
            #pragma unroll
            for (int k = 0; k < 4; k++) {
                int lin = k * 256 + tid;
                int b = lin >> 5, d = lin & 31;
                p0s[b * 32 + d] = g_P0[b * DM + hh * 32 + d];
            }
            __syncthreads();
            #pragma unroll 4
            for (int b = 0; b < 32; b++) {
                float acc = 0.0f;
                #pragma unroll
                for (int d = 0; d < 32; d++)
                    acc = fmaf(p0s[b * 32 + d], wk[d * 256 + tid], acc);
                g_GPb[(b * H + hh) * DM + tid] = acc;
            }
        }
    }
    gridbar(2);

    // ================= Phase 2: delta + weight-dependent outputs =================
    {
        int lt = bid & 7;                    // l' tile (32 l')
        int bg = bid >> 3;                   // batch pair 0..15
        int b0 = bg * 2;

        #pragma unroll
        for (int k = 0; k < 16; k++)
            sm.d.gps[k * 256 + tid] = g_GPb[(size_t)b0 * H * DM + k * 256 + tid];
        __syncthreads();

        // sgp[k] = sum_e gps[k][e], k = bsel*8+h
        {
            int k = tid >> 4, sub = tid & 15;
            float part = 0.0f;
            #pragma unroll
            for (int m = 0; m < 16; m++) part += sm.d.gps[k * 256 + sub * 16 + m];
            #pragma unroll
            for (int off = 8; off > 0; off >>= 1)
                part += __shfl_down_sync(0xffffffffu, part, off, 16);
            if (sub == 0) sm.d.sgp[k] = part;
        }

        int lo = tid & 31, p = tid >> 5;
        int lp = lt * 32 + lo;
        int l = 256 + lp;

        float sdg0[8], sdg1[8], sgq[8];
        #pragma unroll
        for (int h = 0; h < 8; h++) { sdg0[h] = 0.0f; sdg1[h] = 0.0f; sgq[h] = 0.0f; }
        float sd0 = 0.0f, sd1 = 0.0f;

        const float* st0 = state + (size_t)b0 * EN * DX;
        const float* st1 = st0 + (size_t)EN * DX;
        const float* ob0 = obs + (size_t)b0 * EN * DZ;
        const float* ob1 = ob0 + (size_t)EN * DZ;

        #pragma unroll 4
        for (int j = 0; j < 32; j++) {
            int e = p * 32 + j;
            float D0 = st0[(size_t)e * DX + l] - ob0[(size_t)e * DZ + lp];
            float D1 = st1[(size_t)e * DX + l] - ob1[(size_t)e * DZ + lp];
            sd0 += D0; sd1 += D1;
            #pragma unroll
            for (int h = 0; h < 8; h++) {
                float g = g_GQT[(h * DM + e) * LQ + lp];
                sgq[h] += g;
                sdg0[h] = fmaf(D0, g + sm.d.gps[h * DM + e], sdg0[h]);
                sdg1[h] = fmaf(D1, g + sm.d.gps[H * DM + h * DM + e], sdg1[h]);
            }
        }

        #pragma unroll
        for (int h = 0; h < 8; h++) {
            sm.d.red[h * 256 + tid]        = sdg0[h];
            sm.d.red[(8 + h) * 256 + tid]  = sdg1[h];
            sm.d.red[(16 + h) * 256 + tid] = sgq[h];
        }
        sm.d.red[24 * 256 + tid] = sd0;
        sm.d.red[25 * 256 + tid] = sd1;
        __syncthreads();

        if (tid < 64) {
            int bsel = tid >> 5, lo2 = tid & 31;
            int lp2 = lt * 32 + lo2;
            int l2 = 256 + lp2;
            int b = b0 + bsel;
            float sd = 0.0f;
            #pragma unroll
            for (int q = 0; q < 8; q++) sd += sm.d.red[(24 + bsel) * 256 + q * 32 + lo2];
            float md = sd * (1.0f / 256.0f);
            float wsum = 0.0f;
            #pragma unroll
            for (int h = 0; h < 8; h++) {
                float sdg = 0.0f, sq = 0.0f;
                #pragma unroll
                for (int q = 0; q < 8; q++) {
                    sdg += sm.d.red[(bsel * 8 + h) * 256 + q * 32 + lo2];
                    sq  += sm.d.red[(16 + h) * 256 + q * 32 + lo2];
                }
                float sg = sq + sm.d.sgp[bsel * 8 + h];
                float delta = (sdg - md * sg) * 0.17677669529663688f;   // 1/sqrt(32)
                wsum += 1.0f / (1.0f + expf(-delta));
            }
            float w = wsum * 0.125f;
            sm.d.wsh[bsel * 32 + lo2] = w;
            if (att) {
                size_t rowbase = ((size_t)(b * 512 + l2)) * 768;
                att[rowbase + l2]       = w;          // state key
                att[rowbase + l2 + 256] = 1.0f - w;   // obs key
            }
        }
        __syncthreads();

        // fused new_state for l >= 256 (columns are L1-hot from the delta loop)
        if (ns != nullptr) {
            float w0 = sm.d.wsh[lo];
            float w1 = sm.d.wsh[32 + lo];
            float* n0 = ns + (size_t)b0 * EN * DX;
            float* n1 = n0 + (size_t)EN * DX;
            #pragma unroll 4
            for (int j = 0; j < 32; j++) {
                int e = p * 32 + j;
                float s0 = st0[(size_t)e * DX + l], o0 = ob0[(size_t)e * DZ + lp];
                float s1 = st1[(size_t)e * DX + l], o1 = ob1[(size_t)e * DZ + lp];
                n0[(size_t)e * DX + l] = o0 + w0 * (s0 - o0);
                n1[(size_t)e * DX + l] = o1 + w1 * (s1 - o1);
            }
        }
    }

    // ================= Finalize: last arriver resets counters for next replay =================
    __syncthreads();
    if (tid == 0) {
        __threadfence();
        unsigned n = atomicAdd(&g_arrive, 1u) + 1u;
        if (n == 3u * NB) {
            g_arrive = 0u;
            g_work = 0u;
            g_release = 0u;
            __threadfence();
        }
    }
}

// ----------------------------------------------------------------
extern "C" void kernel_launch(void* const* d_in, const int* in_sizes, int n_in,
                              void* d_out, int out_size) {
    const float* state = (const float*)d_in[0];
    const float* obs   = (const float*)d_in[1];
    const float* Qp    = (const float*)d_in[2];
    const float* Wq    = (const float*)d_in[3];
    const float* bq    = (const float*)d_in[4];
    const float* Wk    = (const float*)d_in[5];
    // bk (d_in[6]) provably cancels in the masked softmax — unused.
    float* out = (float*)d_out;

    const int NS = B * EN * DX;        // 4,194,304
    const int AT = B * DX * (DX + DZ); // 12,582,912

    float* ns  = nullptr;
    float* att = nullptr;
    if (out_size >= NS + AT)      { ns = out; att = out + NS; }
    else if (out_size == AT)      { att = out; }
    else                          { ns = out; }

    k_fused<<<NB, 256>>>(state, obs, Qp, Wq, bq, Wk, ns, att);
}

// round 4
// speedup vs baseline: 1.2490x; 1.1488x over previous
#include <cuda_runtime.h>
#include <math.h>

#define B   32
#define EN  256
#define DX  512
#define DZ  256
#define DM  256
#define H   8
#define LQ  256   // active queries: l in [256,512)
#define NB  256   // persistent blocks; launch_bounds(256,2) -> 296 slots >= 256, all co-resident

// scratch (device globals; no allocation allowed)
__device__ __align__(16) float g_Q0[LQ*DM];      // Q0[l'][d] = Qp[256+l']@Wq^T + bq
__device__ __align__(16) float g_P0[B*DM];       // P0[b][d]  = pe[b]@Wq^T
__device__ __align__(16) float g_GQT[H*DM*LQ];   // [h][e][l']
__device__ __align__(16) float g_GPb[B*H*DM];    // [b][h][e]
__device__ unsigned g_arrive;                    // barrier arrivals (monotonic per launch)
__device__ volatile unsigned g_release;          // barrier release phase
__device__ unsigned g_work;                      // work-steal counter for phase 0

__device__ __forceinline__ void gridbar(unsigned phase) {
    __syncthreads();
    if (threadIdx.x == 0) {
        __threadfence();
        unsigned n = atomicAdd(&g_arrive, 1u) + 1u;
        if (n == phase * NB) {
            __threadfence();
            g_release = phase;
        } else {
            while (g_release < phase) __nanosleep(32);
        }
    }
    __syncthreads();
    __threadfence();
}

__global__ __launch_bounds__(256, 2) void k_fused(
    const float* __restrict__ state, const float* __restrict__ obs,
    const float* __restrict__ Qp, const float* __restrict__ Wq,
    const float* __restrict__ bq, const float* __restrict__ Wk,
    float* __restrict__ ns, float* __restrict__ att)
{
    __shared__ union {
        float rowS[32 * DM];                              // phase 0a: 32KB
        float gk[8192 + 1024];                            // phase 1:  36KB
        struct { float gps[H*DM]; float red[17*256];
                 float sgp[8]; float wsh[32]; } d;        // phase 2: ~25.8KB
    } sm;

    const int bid = blockIdx.x;
    const int tid = threadIdx.x;
    const int lane = tid & 31;

    // ================= Phase 0a: Q0 / P0 projection (blocks 0..71) =================
    if (bid < 72) {
        int rt = bid >> 3, dt = bid & 7;      // rt 0..8 (32 rows), dt 0..7 (32 d)
        const float nl = -(logf(10000.0f) / (float)DM);
        #pragma unroll
        for (int k = 0; k < 32; k++) {
            int lin = k * 256 + tid;
            int r = lin >> 8, c = lin & 255;
            int gi = rt * 32 + r;
            float v;
            if (gi < 256) {
                v = Qp[(256 + gi) * DM + c];
            } else {
                int p = gi - 256;             // pe row (= batch index)
                int i = c >> 1;
                float dv = expf(nl * (float)(2 * i));
                float arg = (float)p * dv;
                v = (c & 1) ? cosf(arg) : sinf(arg);
            }
            sm.rowS[r * DM + c] = v;
        }
        __syncthreads();

        int d = dt * 32 + lane;
        int rbase = (tid >> 5) * 4;
        float bias = (rt < 8) ? bq[d] : 0.0f;   // pe rows (P0) exclude bq
        float acc[4];
        #pragma unroll
        for (int r = 0; r < 4; r++) acc[r] = bias;

        const float4* Wq4 = (const float4*)(Wq + (size_t)d * DM);
        #pragma unroll 8
        for (int c4 = 0; c4 < 64; c4++) {
            float4 w4 = Wq4[c4];
            #pragma unroll
            for (int r = 0; r < 4; r++) {
                float4 r4 = ((const float4*)&sm.rowS[(rbase + r) * DM])[c4];
                acc[r] += r4.x * w4.x + r4.y * w4.y + r4.z * w4.z + r4.w * w4.w;
            }
        }
        #pragma unroll
        for (int r = 0; r < 4; r++) {
            int gi = rt * 32 + rbase + r;
            if (gi < 256) g_Q0[gi * DM + d] = acc[r];
            else          g_P0[(gi - 256) * DM + d] = acc[r];
        }
    }

    // ================= Phase 0b: per-warp work-steal streaming (all blocks) ==========
    // att zero-fill (+ diag 1.0 for l<256) and new_state l<256 copy.
    {
        const int Ua = att ? 2048 : 0;    // units of 8 att rows (row = 192 float4)
        const int Un = ns  ? 256  : 0;    // units of 32 (b,e)-rows x 64 float4
        const int total = Ua + Un;
        for (;;) {
            unsigned u;
            if (lane == 0) u = atomicAdd(&g_work, 1u);
            u = __shfl_sync(0xffffffffu, u, 0);
            if (u >= (unsigned)total) break;
            if (u < (unsigned)Ua) {
                int r0 = (int)u * 8;
                #pragma unroll
                for (int k = 0; k < 8; k++) {
                    int row = r0 + k;               // row = b*512 + l
                    int l = row & 511;
                    size_t base = (size_t)row * 192;
                    int c = l >> 2;                 // identity float4 col (valid when l<256)
                    #pragma unroll
                    for (int k2 = 0; k2 < 6; k2++) {
                        float4 v = make_float4(0.f, 0.f, 0.f, 0.f);
                        if (l < 256 && (k2 * 32 + lane) == c)
                            ((float*)&v)[l & 3] = 1.0f;
                        ((float4*)att)[base + k2 * 32 + lane] = v;
                    }
                }
            } else {
                int re0 = ((int)u - Ua) * 32;       // (b*EN+e) row base
                #pragma unroll 4
                for (int m = 0; m < 32; m++) {
                    size_t rb = (size_t)(re0 + m) * 128;
                    float4 a0 = ((const float4*)state)[rb + lane];
                    float4 a1 = ((const float4*)state)[rb + lane + 32];
                    ((float4*)ns)[rb + lane]      = a0;
                    ((float4*)ns)[rb + lane + 32] = a1;
                }
            }
        }
    }
    gridbar(1);

    // ================= Phase 1: GQT (all blocks) + GPb (blocks 248..255) =============
    {
        int h = bid >> 5, et = bid & 31;    // e tile of 8
        float* wks = sm.gk;                 // [8 ee][32 d]
        {
            int ee = tid >> 5, d = tid & 31;
            wks[ee * 32 + d] = Wk[(h * 32 + d) * DM + et * 8 + ee];
        }
        __syncthreads();

        float4 q4[8];
        const float4* q0p = (const float4*)(g_Q0 + (size_t)tid * DM + h * 32);
        #pragma unroll
        for (int j = 0; j < 8; j++) q4[j] = q0p[j];

        #pragma unroll
        for (int ee = 0; ee < 8; ee++) {
            float acc = 0.0f;
            const float4* wr = (const float4*)&wks[ee * 32];
            #pragma unroll
            for (int j = 0; j < 8; j++) {
                float4 w4 = wr[j];
                acc += q4[j].x * w4.x + q4[j].y * w4.y + q4[j].z * w4.z + q4[j].w * w4.w;
            }
            g_GQT[(h * DM + et * 8 + ee) * LQ + tid] = acc;
        }
        __syncthreads();

        if (bid >= 248) {
            int hh = bid - 248;              // head for GPb
            float* wk  = sm.gk;              // [32 d][256 e]
            float* p0s = sm.gk + 8192;       // [32 b][32 d]
            #pragma unroll
            for (int d = 0; d < 32; d++)
                wk[d * 256 + tid] = Wk[(hh * 32 + d) * DM + tid];
            #pragma unroll
            for (int k = 0; k < 4; k++) {
                int lin = k * 256 + tid;
                int b = lin >> 5, d = lin & 31;
                p0s[b * 32 + d] = g_P0[b * DM + hh * 32 + d];
            }
            __syncthreads();
            #pragma unroll 4
            for (int b = 0; b < 32; b++) {
                float acc = 0.0f;
                #pragma unroll
                for (int d = 0; d < 32; d++)
                    acc = fmaf(p0s[b * 32 + d], wk[d * 256 + tid], acc);
                g_GPb[(b * H + hh) * DM + tid] = acc;
            }
        }
    }
    gridbar(2);

    // ================= Phase 2: delta + weight-dependent outputs =====================
    {
        int b  = bid >> 3;                   // batch 0..31
        int lt = bid & 7;                    // l' tile (32 l')

        #pragma unroll
        for (int k = 0; k < 8; k++)
            sm.d.gps[k * 256 + tid] = g_GPb[(size_t)b * H * DM + k * 256 + tid];
        __syncthreads();

        // sgp[h] = sum_e gps[h][e] : warp w handles h=w
        {
            int w = tid >> 5;
            float part = 0.0f;
            #pragma unroll
            for (int k = 0; k < 8; k++) part += sm.d.gps[w * 256 + lane + 32 * k];
            #pragma unroll
            for (int off = 16; off > 0; off >>= 1)
                part += __shfl_down_sync(0xffffffffu, part, off);
            if (lane == 0) sm.d.sgp[w] = part;
        }

        int lo = lane, p = tid >> 5;
        int lp = lt * 32 + lo;
        int l = 256 + lp;

        float sdg[8], sgq[8];
        #pragma unroll
        for (int h = 0; h < 8; h++) { sdg[h] = 0.0f; sgq[h] = 0.0f; }
        float sd = 0.0f;

        const float* st = state + (size_t)b * EN * DX;
        const float* ob = obs   + (size_t)b * EN * DZ;

        #pragma unroll 4
        for (int j = 0; j < 32; j++) {
            int e = p * 32 + j;
            float D = st[(size_t)e * DX + l] - ob[(size_t)e * DZ + lp];
            sd += D;
            #pragma unroll
            for (int h = 0; h < 8; h++) {
                float g = g_GQT[(h * DM + e) * LQ + lp];
                sgq[h] += g;
                sdg[h] = fmaf(D, g + sm.d.gps[h * DM + e], sdg[h]);
            }
        }

        #pragma unroll
        for (int h = 0; h < 8; h++) {
            sm.d.red[h * 256 + tid]       = sdg[h];
            sm.d.red[(8 + h) * 256 + tid] = sgq[h];
        }
        sm.d.red[16 * 256 + tid] = sd;
        __syncthreads();

        if (tid < 32) {
            int lo2 = tid;
            int lp2 = lt * 32 + lo2;
            int l2 = 256 + lp2;
            float sdt = 0.0f;
            #pragma unroll
            for (int q = 0; q < 8; q++) sdt += sm.d.red[16 * 256 + q * 32 + lo2];
            float md = sdt * (1.0f / 256.0f);
            float wsum = 0.0f;
            #pragma unroll
            for (int h = 0; h < 8; h++) {
                float sdgt = 0.0f, sq = 0.0f;
                #pragma unroll
                for (int q = 0; q < 8; q++) {
                    sdgt += sm.d.red[h * 256 + q * 32 + lo2];
                    sq   += sm.d.red[(8 + h) * 256 + q * 32 + lo2];
                }
                float sg = sq + sm.d.sgp[h];
                float delta = (sdgt - md * sg) * 0.17677669529663688f;   // 1/sqrt(32)
                wsum += 1.0f / (1.0f + expf(-delta));
            }
            float w = wsum * 0.125f;
            sm.d.wsh[lo2] = w;
            if (att) {
                size_t rowbase = ((size_t)(b * 512 + l2)) * 768;
                att[rowbase + l2]       = w;          // state key
                att[rowbase + l2 + 256] = 1.0f - w;   // obs key
            }
        }
        __syncthreads();

        // fused new_state for l >= 256 (columns are L1-hot from the delta loop)
        if (ns != nullptr) {
            float w = sm.d.wsh[lo];
            float* n = ns + (size_t)b * EN * DX;
            #pragma unroll 4
            for (int j = 0; j < 32; j++) {
                int e = p * 32 + j;
                float s = st[(size_t)e * DX + l], o = ob[(size_t)e * DZ + lp];
                n[(size_t)e * DX + l] = o + w * (s - o);
            }
        }
    }

    // ================= Finalize: last arriver resets counters for next replay ========
    __syncthreads();
    if (tid == 0) {
        __threadfence();
        unsigned n = atomicAdd(&g_arrive, 1u) + 1u;
        if (n == 3u * NB) {
            g_arrive = 0u;
            g_work = 0u;
            g_release = 0u;
            __threadfence();
        }
    }
}

// ----------------------------------------------------------------
extern "C" void kernel_launch(void* const* d_in, const int* in_sizes, int n_in,
                              void* d_out, int out_size) {
    const float* state = (const float*)d_in[0];
    const float* obs   = (const float*)d_in[1];
    const float* Qp    = (const float*)d_in[2];
    const float* Wq    = (const float*)d_in[3];
    const float* bq    = (const float*)d_in[4];
    const float* Wk    = (const float*)d_in[5];
    // bk (d_in[6]) provably cancels in the masked softmax — unused.
    float* out = (float*)d_out;

    const int NS = B * EN * DX;        // 4,194,304
    const int AT = B * DX * (DX + DZ); // 12,582,912

    float* ns  = nullptr;
    float* att = nullptr;
    if (out_size >= NS + AT)      { ns = out; att = out + NS; }
    else if (out_size == AT)      { att = out; }
    else                          { ns = out; }

    k_fused<<<NB, 256>>>(state, obs, Qp, Wq, bq, Wk, ns, att);
}